// round 12
// baseline (speedup 1.0000x reference)
#include <cuda_runtime.h>
#include <cuda_bf16.h>
#include <cstdint>

#define B_ 4
#define C_ 16
#define H_ 512
#define W_ 512
#define HW_ (H_ * W_)            // 262144
#define NPIX_ (B_ * HW_)         // 1048576
#define EPS_ 1e-10f

// Scratch: packed (priority<<32 | float_bits(Z)) per output pixel. 8 MB.
// Zero at module load; final_kernel re-zeros after consuming -> replay-safe.
__device__ unsigned long long g_scratch[NPIX_];

// ---------------------------------------------------------------------------
// Main: unproject -> last-mask transform -> reproject -> priority scatter.
// 2 px/thread, 2048 blocks (512 px/block, batch-uniform).
// ---------------------------------------------------------------------------
__global__ void __launch_bounds__(256)
main_kernel(const float* __restrict__ depth,
            const float* __restrict__ K,
            const float* __restrict__ T,
            const void* __restrict__ masks) {
    __shared__ float4 sT4[C_ * 4];   // T rows as float4: sT4[c*4 + r]
    __shared__ float  sK[9];
    __shared__ float  sKi[9];
    __shared__ int    s_bad;

    const int tid  = threadIdx.x;
    const int base = blockIdx.x * 512;
    const int b    = base >> 18;               // batch (constant per block)

    // ---- Per-thread global loads first (in flight during prologue) --------
    const int idx = base + tid * 2;
    const int rem = idx & (HW_ - 1);
    const long mbase = (long)b * (C_ * HW_) + rem;

    const float2 d2 = *(const float2*)(depth + idx);
    int2 g1[4];
    {
        const int* m = (const int*)masks;
        #pragma unroll
        for (int j = 0; j < 4; ++j)
            g1[j] = __ldg((const int2*)(m + mbase + (long)(12 + j) * HW_));
    }

    // ---- Prologue: stage K, K^-1, T in shared; sniff mask dtype -----------
    if (tid == 0) {
        s_bad = 0;
        const float* k = K + b * 9;
        float a = k[0], bb = k[1], c = k[2];
        float d = k[3], e  = k[4], f = k[5];
        float g = k[6], h  = k[7], i = k[8];
        float A  =  (e * i - f * h);
        float Bc = -(d * i - f * g);
        float Cc =  (d * h - e * g);
        float det = a * A + bb * Bc + c * Cc;
        float inv = 1.0f / det;
        sKi[0] = A * inv;
        sKi[1] = -(bb * i - c * h) * inv;
        sKi[2] =  (bb * f - c * e) * inv;
        sKi[3] = Bc * inv;
        sKi[4] =  (a * i - c * g) * inv;
        sKi[5] = -(a * f - c * d) * inv;
        sKi[6] = Cc * inv;
        sKi[7] = -(a * h - bb * g) * inv;
        sKi[8] =  (a * e - bb * d) * inv;
    }
    if (tid < 64) sT4[tid] = ((const float4*)(T + b * (C_ * 16)))[tid];
    if (tid < 9)  sK[tid]  = K[b * 9 + tid];
    if (tid >= 128 && tid < 256) {
        unsigned wv = ((const unsigned*)masks)[tid - 128];
        if (wv > 1u) atomicOr(&s_bad, 1);
    }
    __syncthreads();
    const bool mask_is_i32 = (s_bad == 0);

    const int v = rem >> 9;
    const int u = rem & (W_ - 1);
    const float dd[2] = {d2.x, d2.y};

    // Last set channel per pixel. "Any unresolved" test is OR, not AND.
    int cw[2] = {-1, -1};
    if (mask_is_i32) {
        const int* m = (const int*)masks;
        #pragma unroll
        for (int j = 3; j >= 0; --j) {        // channels 15..12 (preloaded)
            if (cw[0] < 0 && g1[j].x) cw[0] = 12 + j;
            if (cw[1] < 0 && g1[j].y) cw[1] = 12 + j;
        }
        if ((cw[0] | cw[1]) < 0) {            // channels 11..4
            int2 a[8];
            #pragma unroll
            for (int j = 0; j < 8; ++j)
                a[j] = __ldg((const int2*)(m + mbase + (long)(4 + j) * HW_));
            #pragma unroll
            for (int j = 7; j >= 0; --j) {
                if (cw[0] < 0 && a[j].x) cw[0] = 4 + j;
                if (cw[1] < 0 && a[j].y) cw[1] = 4 + j;
            }
            if ((cw[0] | cw[1]) < 0) {        // channels 3..0
                int2 a2[4];
                #pragma unroll
                for (int j = 0; j < 4; ++j)
                    a2[j] = __ldg((const int2*)(m + mbase + (long)j * HW_));
                #pragma unroll
                for (int j = 3; j >= 0; --j) {
                    if (cw[0] < 0 && a2[j].x) cw[0] = j;
                    if (cw[1] < 0 && a2[j].y) cw[1] = j;
                }
            }
        }
    } else {
        const unsigned char* mb = (const unsigned char*)masks;
        {   // channels 15..12
            unsigned short a[4];
            #pragma unroll
            for (int j = 0; j < 4; ++j)
                a[j] = *(const unsigned short*)(mb + mbase + (long)(12 + j) * HW_);
            #pragma unroll
            for (int j = 3; j >= 0; --j) {
                if (cw[0] < 0 && (a[j] & 0x00ffu)) cw[0] = 12 + j;
                if (cw[1] < 0 && (a[j] & 0xff00u)) cw[1] = 12 + j;
            }
        }
        if ((cw[0] | cw[1]) < 0) {
            unsigned short a[8];
            #pragma unroll
            for (int j = 0; j < 8; ++j)
                a[j] = *(const unsigned short*)(mb + mbase + (long)(4 + j) * HW_);
            #pragma unroll
            for (int j = 7; j >= 0; --j) {
                if (cw[0] < 0 && (a[j] & 0x00ffu)) cw[0] = 4 + j;
                if (cw[1] < 0 && (a[j] & 0xff00u)) cw[1] = 4 + j;
            }
            if ((cw[0] | cw[1]) < 0) {
                unsigned short a2[4];
                #pragma unroll
                for (int j = 0; j < 4; ++j)
                    a2[j] = *(const unsigned short*)(mb + mbase + (long)j * HW_);
                #pragma unroll
                for (int j = 3; j >= 0; --j) {
                    if (cw[0] < 0 && (a2[j] & 0x00ffu)) cw[0] = j;
                    if (cw[1] < 0 && (a2[j] & 0xff00u)) cw[1] = j;
                }
            }
        }
    }

    const float vf = (float)v;
    #pragma unroll
    for (int p = 0; p < 2; ++p) {
        const float uf = (float)(u + p);
        const float d  = dd[p];

        float x = (sKi[0] * uf + sKi[1] * vf + sKi[2]) * d;
        float y = (sKi[3] * uf + sKi[4] * vf + sKi[5]) * d;
        float z = (sKi[6] * uf + sKi[7] * vf + sKi[8]) * d;

        const int c = cw[p];
        if (c >= 0) {
            const float4 r0 = sT4[c * 4 + 0];
            const float4 r1 = sT4[c * 4 + 1];
            const float4 r2 = sT4[c * 4 + 2];
            const float4 r3 = sT4[c * 4 + 3];
            float tx = r0.x * x + r0.y * y + r0.z * z + r0.w;
            float ty = r1.x * x + r1.y * y + r1.z * z + r1.w;
            float tz = r2.x * x + r2.y * y + r2.z * z + r2.w;
            float tw = r3.x * x + r3.y * y + r3.z * z + r3.w;
            float inv = 1.0f / (tw + EPS_);
            x = tx * inv;
            y = ty * inv;
            z = tz * inv;
        }

        float phx = sK[0] * x + sK[1] * y + sK[2] * z;
        float phy = sK[3] * x + sK[4] * y + sK[5] * z;
        float phz = sK[6] * x + sK[7] * y + sK[8] * z;
        float invz = 1.0f / (phz + EPS_);
        float px = phx * invz;
        float py = phy * invz;

        int ui = (int)fminf(fmaxf(px, 0.0f), (float)(W_ - 1));
        int vi = (int)fminf(fmaxf(py, 0.0f), (float)(H_ - 1));

        unsigned long long pkt =
            ((unsigned long long)(unsigned)(rem + p + 1) << 32) |
            (unsigned long long)__float_as_uint(z);
        atomicMax(&g_scratch[b * HW_ + vi * W_ + ui], pkt);
    }

    // Signal PDL: this CTA's scatter contribution is done.
    cudaTriggerProgrammaticLaunchCompletion();
}

// ---------------------------------------------------------------------------
// Final: resolve scatter else passthrough depth; re-zero scratch.
// Launched with PDL: starts ramping while main runs, blocks on the
// dependency sync until ALL of main's CTAs completed (atomics visible).
// ---------------------------------------------------------------------------
__global__ void __launch_bounds__(256)
final_kernel(const float* __restrict__ depth,
             float* __restrict__ out) {
    const int i2 = (blockIdx.x * 256 + threadIdx.x) * 2;

    // Overlap: depth is read-only input, safe to load BEFORE the sync.
    const float2 dp = *(const float2*)(depth + i2);

    cudaGridDependencySynchronize();

    ulonglong2 s = *(ulonglong2*)&g_scratch[i2];

    float2 o;
    o.x = s.x ? __uint_as_float((unsigned)s.x) : dp.x;
    o.y = s.y ? __uint_as_float((unsigned)s.y) : dp.y;
    *(float2*)(out + i2) = o;

    const ulonglong2 zz = {0ull, 0ull};
    *(ulonglong2*)&g_scratch[i2] = zz;
}

extern "C" void kernel_launch(void* const* d_in, const int* in_sizes, int n_in,
                              void* d_out, int out_size) {
    const float* depth = (const float*)d_in[0];
    const float* K     = (const float*)d_in[1];
    const float* T     = (const float*)d_in[2];
    const void*  masks = d_in[3];
    float* out = (float*)d_out;

    main_kernel<<<NPIX_ / 512, 256>>>(depth, K, T, masks);

    // PDL launch of final: overlaps its launch/ramp with main's execution.
    cudaLaunchConfig_t cfg = {};
    cfg.gridDim  = dim3(NPIX_ / 512, 1, 1);
    cfg.blockDim = dim3(256, 1, 1);
    cfg.dynamicSmemBytes = 0;
    cfg.stream = 0;
    cudaLaunchAttribute attrs[1];
    attrs[0].id = cudaLaunchAttributeProgrammaticStreamSerialization;
    attrs[0].val.programmaticStreamSerializationAllowed = 1;
    cfg.attrs = attrs;
    cfg.numAttrs = 1;
    cudaLaunchKernelEx(&cfg, final_kernel, depth, out);
}